// round 16
// baseline (speedup 1.0000x reference)
#include <cuda_runtime.h>
#include <cuda_fp16.h>
#include <math.h>
#include <stdint.h>

// ---------------- problem constants ----------------
#define T_SEQ   2048
#define DMODEL  2048
#define NH      16
#define NKV     4
#define DH      128
#define BATCH   2
#define NROWS   (BATCH * T_SEQ)   // 4096
#define KDIM    2048
#define KC      64                // K chunk (64 fp16 = 128B rows)
#define NCHUNK  (KDIM / KC)       // 32
#define QKVW    3072              // merged Q|K|V output width
#define LDQKV   3072

typedef __half fp16;

// ---------------- scratch (device globals; no runtime alloc) ----------------
__device__ float g_rc[T_SEQ * 64];
__device__ float g_rs[T_SEQ * 64];

__device__ fp16 g_xhi  [(size_t)NROWS * KDIM];
__device__ fp16 g_qkvhi[(size_t)NROWS * QKVW];   // cols: 0..2047 Q | 2048..2559 K | 2560..3071 V
__device__ fp16 g_aohi [(size_t)NROWS * KDIM];
__device__ fp16 g_wqkvth[(size_t)QKVW * KDIM];   // rows: Wq^T | Wk^T | Wv^T
__device__ fp16 g_woth [(size_t)2048 * KDIM];

// ---------------- PTX helpers ----------------
__device__ __forceinline__ uint32_t smem_u32(const void* p) {
    uint32_t a;
    asm("{ .reg .u64 t; cvta.to.shared.u64 t, %1; cvt.u32.u64 %0, t; }" : "=r"(a) : "l"(p));
    return a;
}
__device__ __forceinline__ void cp16(uint32_t dst, const void* src) {
    asm volatile("cp.async.cg.shared.global [%0], [%1], 16;" :: "r"(dst), "l"(src));
}
__device__ __forceinline__ void ldm_x4(uint32_t* r, uint32_t addr) {
    asm volatile("ldmatrix.sync.aligned.m8n8.x4.shared.b16 {%0,%1,%2,%3}, [%4];"
                 : "=r"(r[0]), "=r"(r[1]), "=r"(r[2]), "=r"(r[3]) : "r"(addr));
}
__device__ __forceinline__ void ldm_x4t(uint32_t* r, uint32_t addr) {
    asm volatile("ldmatrix.sync.aligned.m8n8.x4.trans.shared.b16 {%0,%1,%2,%3}, [%4];"
                 : "=r"(r[0]), "=r"(r[1]), "=r"(r[2]), "=r"(r[3]) : "r"(addr));
}
__device__ __forceinline__ void mma_f16(float* d, const uint32_t* a,
                                        uint32_t b0, uint32_t b1) {
    asm volatile(
        "mma.sync.aligned.m16n8k16.row.col.f32.f16.f16.f32 "
        "{%0,%1,%2,%3}, {%4,%5,%6,%7}, {%8,%9}, {%0,%1,%2,%3};"
        : "+f"(d[0]), "+f"(d[1]), "+f"(d[2]), "+f"(d[3])
        : "r"(a[0]), "r"(a[1]), "r"(a[2]), "r"(a[3]), "r"(b0), "r"(b1));
}
__device__ __forceinline__ uint32_t packh(float a, float b) {
    uint32_t lo = (uint32_t)__half_as_ushort(__float2half_rn(a));
    uint32_t hi = (uint32_t)__half_as_ushort(__float2half_rn(b));
    return lo | (hi << 16);
}
// swizzled byte offset, 256B rows (attention tiles)
__device__ __forceinline__ uint32_t swz256(int row, int c) {
    return (uint32_t)(row * 256 + ((c ^ (row & 7)) << 4));
}
// swizzled byte offset, 128B rows (GEMM KC=64 tiles), c = 16B chunk 0..7
__device__ __forceinline__ uint32_t swz128(int row, int c) {
    return (uint32_t)(row * 128 + ((c ^ (row & 7)) << 4));
}

// ---------------- RoPE table ----------------
__global__ void rope_table_kernel() {
    int idx = blockIdx.x * 256 + threadIdx.x;
    if (idx >= T_SEQ * 64) return;
    int t = idx >> 6;
    int j = idx & 63;
    double inv = pow(10000.0, -(double)j / 64.0);
    double f   = (double)t * inv;
    g_rc[idx] = (float)cos(f);
    g_rs[idx] = (float)sin(f);
}

// ---------------- fp32 -> fp16 convert ----------------
__global__ void conv_h_kernel(const float* __restrict__ src, fp16* __restrict__ hi) {
    int i = blockIdx.x * 256 + threadIdx.x;
    float4 v = ((const float4*)src)[i];
    __half2* hp = (__half2*)(hi + (size_t)i * 4);
    hp[0] = __half2(__float2half_rn(v.x), __float2half_rn(v.y));
    hp[1] = __half2(__float2half_rn(v.z), __float2half_rn(v.w));
}

// ---------------- fused W_q|W_k|W_v transpose (fp16) ----------------
__global__ void wtrans_qkv_kernel(const float* __restrict__ Wq,
                                  const float* __restrict__ Wk,
                                  const float* __restrict__ Wv,
                                  fp16* __restrict__ Thi) {
    __shared__ float t[32][33];
    int bx = blockIdx.x;
    const float* W;
    int N, n0, outoff;
    if (bx < 64)      { W = Wq; N = 2048; n0 = bx * 32;        outoff = 0;    }
    else if (bx < 80) { W = Wk; N = 512;  n0 = (bx - 64) * 32; outoff = 2048; }
    else              { W = Wv; N = 512;  n0 = (bx - 80) * 32; outoff = 2560; }
    int k0 = blockIdx.y * 32;
    int tx = threadIdx.x, ty = threadIdx.y;
#pragma unroll
    for (int i = ty; i < 32; i += 8)
        t[i][tx] = W[(size_t)(k0 + i) * N + n0 + tx];
    __syncthreads();
#pragma unroll
    for (int i = ty; i < 32; i += 8)
        Thi[(size_t)(outoff + n0 + i) * KDIM + k0 + tx] = __float2half_rn(t[tx][i]);
}

// ---------------- single W transpose (fp16) ----------------
__global__ void wtrans_kernel(const float* __restrict__ W,
                              fp16* __restrict__ Thi, int N) {
    __shared__ float t[32][33];
    int n0 = blockIdx.x * 32, k0 = blockIdx.y * 32;
    int tx = threadIdx.x, ty = threadIdx.y;
#pragma unroll
    for (int i = ty; i < 32; i += 8)
        t[i][tx] = W[(size_t)(k0 + i) * N + n0 + tx];
    __syncthreads();
#pragma unroll
    for (int i = ty; i < 32; i += 8)
        Thi[(size_t)(n0 + i) * KDIM + k0 + tx] = __float2half_rn(t[tx][i]);
}

// ---------------- HMMA fp16 GEMM (KC=64, 3-stage, occ 2, hoisted addressing) ----------------
#define GEMM_SMEM (3 * 2 * 16384)     // 98304

__device__ __forceinline__ void prefetch_hoisted(
    uint32_t bufb, const char* agb, const char* bgb, uint32_t soff, size_t go) {
#pragma unroll
    for (int i = 0; i < 4; i++) {
        cp16(bufb + soff + i * 4096,         agb + go + (size_t)i * 131072);
        cp16(bufb + 16384 + soff + i * 4096, bgb + go + (size_t)i * 131072);
    }
}

// ropeLimit: apply RoPE to output cols < ropeLimit
__global__ __launch_bounds__(256, 2)
void tc_gemm(const fp16* __restrict__ Ahi, const fp16* __restrict__ Bhi,
             float* __restrict__ C, fp16* __restrict__ Chi,
             int ldC, int ropeLimit) {
    extern __shared__ char sm[];
    uint32_t sb = smem_u32(sm);
    const int tid = threadIdx.x;
    const int wid = tid >> 5, lane = tid & 31;
    const int wm = wid & 3, wn = wid >> 2;
    const int grp = lane >> 2, tig = lane & 3;
    const int bn = blockIdx.x * 128;
    const int bm = blockIdx.y * 128;

    float acc[2][8][4];
#pragma unroll
    for (int i = 0; i < 2; i++)
#pragma unroll
        for (int j = 0; j < 8; j++)
#pragma unroll
            for (int q = 0; q < 4; q++) acc[i][j][q] = 0.f;

    const int lrow = lane & 15;
    const int lhalf = (lane >> 4) & 1;

    const int prow = tid >> 3, pc16 = tid & 7;
    const char* agb = (const char*)(Ahi + (size_t)(bm + prow) * KDIM + pc16 * 8);
    const char* bgb = (const char*)(Bhi + (size_t)(bn + prow) * KDIM + pc16 * 8);
    const uint32_t soff = swz128(prow, pc16);

    prefetch_hoisted(sb,         agb, bgb, soff, 0);
    asm volatile("cp.async.commit_group;");
    prefetch_hoisted(sb + 32768, agb, bgb, soff, (size_t)KC * 2);
    asm volatile("cp.async.commit_group;");

    for (int c = 0; c < NCHUNK; c++) {
        if (c + 1 < NCHUNK) asm volatile("cp.async.wait_group 1;");
        else                asm volatile("cp.async.wait_group 0;");
        __syncthreads();
        if (c + 2 < NCHUNK) {
            prefetch_hoisted(sb + ((c + 2) % 3) * 32768, agb, bgb, soff,
                             (size_t)(c + 2) * KC * 2);
            asm volatile("cp.async.commit_group;");
        }

        uint32_t tb = sb + (c % 3) * 32768;
#pragma unroll
        for (int ka = 0; ka < 4; ka++) {
            int kc16 = ka * 2 + lhalf;
            uint32_t ah[2][4];
#pragma unroll
            for (int i = 0; i < 2; i++) {
                int row = wm * 32 + i * 16 + lrow;
                ldm_x4(ah[i], tb + swz128(row, kc16));
            }
#pragma unroll
            for (int jg = 0; jg < 4; jg++) {
                int row = wn * 64 + jg * 16 + lrow;
                uint32_t bh[4];
                ldm_x4(bh, tb + 16384 + swz128(row, kc16));
#pragma unroll
                for (int jo = 0; jo < 2; jo++) {
                    int j = jg * 2 + jo;
#pragma unroll
                    for (int i = 0; i < 2; i++)
                        mma_f16(acc[i][j], ah[i], bh[jo], bh[jo + 2]);
                }
            }
        }
    }

#pragma unroll
    for (int i = 0; i < 2; i++) {
#pragma unroll
        for (int j = 0; j < 8; j++) {
            int row0 = bm + wm * 32 + i * 16 + grp;
            int row1 = row0 + 8;
            int col  = bn + wn * 64 + j * 8 + tig * 2;
            float c0 = acc[i][j][0], c1 = acc[i][j][1];
            float c2 = acc[i][j][2], c3 = acc[i][j][3];
            if (col < ropeLimit) {
                int jj = (col & 127) >> 1;
                int t0 = row0 & (T_SEQ - 1);
                int t1 = row1 & (T_SEQ - 1);
                float ct0 = g_rc[(t0 << 6) + jj], st0 = g_rs[(t0 << 6) + jj];
                float ct1 = g_rc[(t1 << 6) + jj], st1 = g_rs[(t1 << 6) + jj];
                float e0 = c0, o0 = c1, e1 = c2, o1 = c3;
                c0 = e0 * ct0 - o0 * st0;  c1 = e0 * st0 + o0 * ct0;
                c2 = e1 * ct1 - o1 * st1;  c3 = e1 * st1 + o1 * ct1;
            }
            if (Chi) {
                *(__half2*)(Chi + (size_t)row0 * ldC + col) =
                    __half2(__float2half_rn(c0), __float2half_rn(c1));
                *(__half2*)(Chi + (size_t)row1 * ldC + col) =
                    __half2(__float2half_rn(c2), __float2half_rn(c3));
            } else {
                *(float2*)(C + (size_t)row0 * ldC + col) = make_float2(c0, c1);
                *(float2*)(C + (size_t)row1 * ldC + col) = make_float2(c2, c3);
            }
        }
    }
}

// ---------------- HMMA fp16 flash attention (128-key tiles, one softmax per tile) ----------------
// smem: Qhi 32KB + 2 stages x (Khi 32KB + Vhi 32KB) = 163840
#define ATT_SMEM (32768 + 2 * 65536)

__global__ __launch_bounds__(256, 1)
void attn_mma(const fp16* __restrict__ qkvhi, fp16* __restrict__ aoh) {
    extern __shared__ char sm[];
    uint32_t sb = smem_u32(sm);
    const int tid = threadIdx.x, w = tid >> 5, lane = tid & 31;
    const int grp = lane >> 2, tig = lane & 3;
    const int lrow = lane & 15, lhalf = lane >> 4;
    const int qt = (int)gridDim.x - 1 - (int)blockIdx.x;   // largest-work-first
    const int h = blockIdx.y, b = blockIdx.z;
    const int q0 = qt * 128, kvh = h >> 2;
    const float scale = 0.08838834764831845f;
    const float NEG_INF = __int_as_float(0xff800000);

    const uint32_t QH = sb;
    const uint32_t ST = sb + 32768;

    // hoisted per-thread KV addressing: thread step 256 => row += 16
    const int krow = tid >> 4, kc = tid & 15;
    const fp16* kvb = qkvhi + (size_t)b * T_SEQ * LDQKV + 2048 + kvh * DH + kc * 8;
    const uint32_t kvoff = swz256(krow, kc);

    // stage Q tile, then KV tile 0 (128 keys)
#pragma unroll
    for (int i = 0; i < 8; i++) {
        int ck = tid + 256 * i;
        int row = ck >> 4, c = ck & 15;
        size_t src = (size_t)(b * T_SEQ + q0 + row) * LDQKV + h * DH + c * 8;
        cp16(QH + swz256(row, c), qkvhi + src);
    }
    asm volatile("cp.async.commit_group;");
    {
#pragma unroll
        for (int i = 0; i < 8; i++) {
            int jg = krow + 16 * i;          // j0 = 0: jg < 128 -> kpos = jg
            const fp16* s = kvb + (size_t)jg * LDQKV;
            cp16(ST + kvoff + i * 4096,         s);         // Khi
            cp16(ST + 32768 + kvoff + i * 4096, s + 512);   // Vhi
        }
        asm volatile("cp.async.commit_group;");
    }

    asm volatile("cp.async.wait_group 1;");
    __syncthreads();
    uint32_t aqh[8][4];
#pragma unroll
    for (int kcq = 0; kcq < 8; kcq++)
        ldm_x4(aqh[kcq], QH + swz256(w * 16 + lrow, kcq * 2 + lhalf));

    float O[16][4];
#pragma unroll
    for (int t = 0; t < 16; t++)
#pragma unroll
        for (int q = 0; q < 4; q++) O[t][q] = 0.f;
    float m0 = NEG_INF, m1 = NEG_INF, l0 = 0.f, l1 = 0.f;

    const int nt = (qt + 1 < 9) ? (qt + 1) : 9;   // 128-key tiles
    const int r0g = q0 + w * 16 + grp;
    const int r1g = r0g + 8;
    const int rmax = q0 + w * 16 + 15;

    for (int jt = 0; jt < nt; jt++) {
        asm volatile("cp.async.wait_group 0;");
        __syncthreads();
        if (jt + 1 < nt) {
            int j0n = (jt + 1) * 128;
            uint32_t dst = ST + ((jt + 1) & 1) * 65536;
#pragma unroll
            for (int i = 0; i < 8; i++) {
                int jg = j0n + krow + 16 * i;
                int kpos = (jg < 128) ? jg : (jg + 896);
                const fp16* s = kvb + (size_t)kpos * LDQKV;
                cp16(dst + kvoff + i * 4096,         s);
                cp16(dst + 32768 + kvoff + i * 4096, s + 512);
            }
            asm volatile("cp.async.commit_group;");
        }

        const int j0 = jt * 128;
        if (j0 <= rmax) {
            uint32_t tb = ST + (jt & 1) * 65536;
            float S[16][4];
#pragma unroll
            for (int t = 0; t < 16; t++)
#pragma unroll
                for (int q = 0; q < 4; q++) S[t][q] = 0.f;

            // S = Qhi Khi^T per 64-key half (skip fully-masked half; mask fixes S)
#pragma unroll
            for (int half = 0; half < 2; half++) {
                if (j0 + half * 64 <= rmax) {
#pragma unroll
                    for (int kcq = 0; kcq < 8; kcq++) {
#pragma unroll
                        for (int g = 0; g < 4; g++) {
                            int row = half * 64 + g * 16 + lrow;
                            uint32_t koff = swz256(row, kcq * 2 + lhalf);
                            uint32_t bh[4];
                            ldm_x4(bh, tb + koff);
                            int t = half * 8 + 2 * g;
                            mma_f16(S[t],     aqh[kcq], bh[0], bh[2]);
                            mma_f16(S[t + 1], aqh[kcq], bh[1], bh[3]);
                        }
                    }
                }
            }

            // scale + mask + single online softmax over 128 keys
            float tm0 = NEG_INF, tm1 = NEG_INF;
#pragma unroll
            for (int t = 0; t < 16; t++) {
                int c0 = j0 + 8 * t + 2 * tig, c1 = c0 + 1;
                S[t][0] = (c0 > r0g) ? NEG_INF : S[t][0] * scale;
                S[t][1] = (c1 > r0g) ? NEG_INF : S[t][1] * scale;
                S[t][2] = (c0 > r1g) ? NEG_INF : S[t][2] * scale;
                S[t][3] = (c1 > r1g) ? NEG_INF : S[t][3] * scale;
                tm0 = fmaxf(tm0, fmaxf(S[t][0], S[t][1]));
                tm1 = fmaxf(tm1, fmaxf(S[t][2], S[t][3]));
            }
            tm0 = fmaxf(tm0, __shfl_xor_sync(0xffffffffu, tm0, 1));
            tm0 = fmaxf(tm0, __shfl_xor_sync(0xffffffffu, tm0, 2));
            tm1 = fmaxf(tm1, __shfl_xor_sync(0xffffffffu, tm1, 1));
            tm1 = fmaxf(tm1, __shfl_xor_sync(0xffffffffu, tm1, 2));
            float mn0 = fmaxf(m0, tm0), mn1 = fmaxf(m1, tm1);
            float al0 = __expf(m0 - mn0), al1 = __expf(m1 - mn1);
            m0 = mn0;  m1 = mn1;
            float rs0 = 0.f, rs1 = 0.f;
#pragma unroll
            for (int t = 0; t < 16; t++) {
                S[t][0] = __expf(S[t][0] - mn0);
                S[t][1] = __expf(S[t][1] - mn0);
                S[t][2] = __expf(S[t][2] - mn1);
                S[t][3] = __expf(S[t][3] - mn1);
                rs0 += S[t][0] + S[t][1];
                rs1 += S[t][2] + S[t][3];
            }
            rs0 += __shfl_xor_sync(0xffffffffu, rs0, 1);
            rs0 += __shfl_xor_sync(0xffffffffu, rs0, 2);
            rs1 += __shfl_xor_sync(0xffffffffu, rs1, 1);
            rs1 += __shfl_xor_sync(0xffffffffu, rs1, 2);
            l0 = l0 * al0 + rs0;
            l1 = l1 * al1 + rs1;
#pragma unroll
            for (int t = 0; t < 16; t++) {
                O[t][0] *= al0;  O[t][1] *= al0;
                O[t][2] *= al1;  O[t][3] *= al1;
            }

            // O += Phi Vhi over active 16-key groups only
            const int kkmax = min(8, ((rmax - j0) >> 4) + 1);
#pragma unroll
            for (int kk = 0; kk < 8; kk++) {
                if (kk >= kkmax) break;
                uint32_t pha[4];
#pragma unroll
                for (int half = 0; half < 2; half++) {
                    int t = 2 * kk + half;
                    pha[half * 2 + 0] = packh(S[t][0], S[t][1]);
                    pha[half * 2 + 1] = packh(S[t][2], S[t][3]);
                }
#pragma unroll
                for (int g = 0; g < 8; g++) {
                    uint32_t voff = swz256(kk * 16 + lrow, g * 2 + lhalf);
                    uint32_t vh4[4];
                    ldm_x4t(vh4, tb + 32768 + voff);
                    mma_f16(O[2*g],   pha, vh4[0], vh4[1]);
                    mma_f16(O[2*g+1], pha, vh4[2], vh4[3]);
                }
            }
        }
    }

    float il0 = 1.0f / l0, il1 = 1.0f / l1;
    size_t gr0 = (size_t)(b * T_SEQ + r0g);
    size_t gr1 = (size_t)(b * T_SEQ + r1g);
#pragma unroll
    for (int t = 0; t < 16; t++) {
        int col = h * DH + 8 * t + 2 * tig;
        *(__half2*)(aoh + gr0 * KDIM + col) =
            __half2(__float2half_rn(O[t][0] * il0), __float2half_rn(O[t][1] * il0));
        *(__half2*)(aoh + gr1 * KDIM + col) =
            __half2(__float2half_rn(O[t][2] * il1), __float2half_rn(O[t][3] * il1));
    }
}

// ---------------- launch ----------------
extern "C" void kernel_launch(void* const* d_in, const int* in_sizes, int n_in,
                              void* d_out, int out_size) {
    const float* x  = (const float*)d_in[0];
    const float* Wq = (const float*)d_in[1];
    const float* Wk = (const float*)d_in[2];
    const float* Wv = (const float*)d_in[3];
    const float* Wo = (const float*)d_in[4];
    float* out = (float*)d_out;

    fp16 *xhi, *qkvhi, *aohi, *wqkvth, *woth;
    cudaGetSymbolAddress((void**)&xhi,    g_xhi);
    cudaGetSymbolAddress((void**)&qkvhi,  g_qkvhi);
    cudaGetSymbolAddress((void**)&aohi,   g_aohi);
    cudaGetSymbolAddress((void**)&wqkvth, g_wqkvth);
    cudaGetSymbolAddress((void**)&woth,   g_woth);

    cudaFuncSetAttribute(tc_gemm,  cudaFuncAttributeMaxDynamicSharedMemorySize, GEMM_SMEM);
    cudaFuncSetAttribute(attn_mma, cudaFuncAttributeMaxDynamicSharedMemorySize, ATT_SMEM);

    rope_table_kernel<<<512, 256>>>();                                       // 0
    conv_h_kernel<<<8192, 256>>>(x, xhi);                                    // 1
    wtrans_qkv_kernel<<<dim3(96, 64), dim3(32, 8)>>>(Wq, Wk, Wv, wqkvth);    // 2
    tc_gemm<<<dim3(24, 32), 256, GEMM_SMEM>>>(xhi, wqkvth,
                                              nullptr, qkvhi, LDQKV, 2560);  // 3
    attn_mma<<<dim3(16, NH, BATCH), 256, ATT_SMEM>>>(qkvhi, aohi);           // 4
    wtrans_kernel<<<dim3(64, 64), dim3(32, 8)>>>(Wo, woth, 2048);            // 5
    tc_gemm<<<dim3(16, 32), 256, GEMM_SMEM>>>(aohi, woth,
                                              out, nullptr, DMODEL, 0);      // 6
}

// round 17
// speedup vs baseline: 1.0711x; 1.0711x over previous
#include <cuda_runtime.h>
#include <cuda_fp16.h>
#include <math.h>
#include <stdint.h>

// ---------------- problem constants ----------------
#define T_SEQ   2048
#define DMODEL  2048
#define NH      16
#define NKV     4
#define DH      128
#define BATCH   2
#define NROWS   (BATCH * T_SEQ)   // 4096
#define KDIM    2048
#define KC      64                // K chunk (64 fp16 = 128B rows)
#define NCHUNK  (KDIM / KC)       // 32
#define QKVW    3072              // merged Q|K|V output width
#define LDQKV   3072

typedef __half fp16;

// ---------------- scratch (device globals; no runtime alloc) ----------------
__device__ float  g_rc[T_SEQ * 64];
__device__ float  g_rs[T_SEQ * 64];
__device__ double g_inv[64];

__device__ fp16 g_xhi  [(size_t)NROWS * KDIM];
__device__ fp16 g_qkvhi[(size_t)NROWS * QKVW];   // cols: 0..2047 Q | 2048..2559 K | 2560..3071 V
__device__ fp16 g_aohi [(size_t)NROWS * KDIM];
__device__ fp16 g_wqkvth[(size_t)QKVW * KDIM];   // rows: Wq^T | Wk^T | Wv^T
__device__ fp16 g_woth [(size_t)2048 * KDIM];

// ---------------- PTX helpers ----------------
__device__ __forceinline__ uint32_t smem_u32(const void* p) {
    uint32_t a;
    asm("{ .reg .u64 t; cvta.to.shared.u64 t, %1; cvt.u32.u64 %0, t; }" : "=r"(a) : "l"(p));
    return a;
}
__device__ __forceinline__ void cp16(uint32_t dst, const void* src) {
    asm volatile("cp.async.cg.shared.global [%0], [%1], 16;" :: "r"(dst), "l"(src));
}
__device__ __forceinline__ void ldm_x4(uint32_t* r, uint32_t addr) {
    asm volatile("ldmatrix.sync.aligned.m8n8.x4.shared.b16 {%0,%1,%2,%3}, [%4];"
                 : "=r"(r[0]), "=r"(r[1]), "=r"(r[2]), "=r"(r[3]) : "r"(addr));
}
__device__ __forceinline__ void ldm_x4t(uint32_t* r, uint32_t addr) {
    asm volatile("ldmatrix.sync.aligned.m8n8.x4.trans.shared.b16 {%0,%1,%2,%3}, [%4];"
                 : "=r"(r[0]), "=r"(r[1]), "=r"(r[2]), "=r"(r[3]) : "r"(addr));
}
__device__ __forceinline__ void mma_f16(float* d, const uint32_t* a,
                                        uint32_t b0, uint32_t b1) {
    asm volatile(
        "mma.sync.aligned.m16n8k16.row.col.f32.f16.f16.f32 "
        "{%0,%1,%2,%3}, {%4,%5,%6,%7}, {%8,%9}, {%0,%1,%2,%3};"
        : "+f"(d[0]), "+f"(d[1]), "+f"(d[2]), "+f"(d[3])
        : "r"(a[0]), "r"(a[1]), "r"(a[2]), "r"(a[3]), "r"(b0), "r"(b1));
}
__device__ __forceinline__ uint32_t packh(float a, float b) {
    uint32_t lo = (uint32_t)__half_as_ushort(__float2half_rn(a));
    uint32_t hi = (uint32_t)__half_as_ushort(__float2half_rn(b));
    return lo | (hi << 16);
}
// swizzled byte offset, 256B rows (attention tiles)
__device__ __forceinline__ uint32_t swz256(int row, int c) {
    return (uint32_t)(row * 256 + ((c ^ (row & 7)) << 4));
}
// swizzled byte offset, 128B rows (GEMM KC=64 tiles), c = 16B chunk 0..7
__device__ __forceinline__ uint32_t swz128(int row, int c) {
    return (uint32_t)(row * 128 + ((c ^ (row & 7)) << 4));
}

// ---------------- RoPE tables ----------------
// 64 distinct inverse-frequency values, double pow (once per replay, tiny)
__global__ void rope_inv_kernel() {
    int j = threadIdx.x;
    if (j < 64) g_inv[j] = pow(10000.0, -(double)j / 64.0);
}
// cos/sin table: exact double angle + double range reduction + fp32 sincos
__global__ void rope_table_kernel() {
    int idx = blockIdx.x * 256 + threadIdx.x;
    if (idx >= T_SEQ * 64) return;
    int t = idx >> 6;
    int j = idx & 63;
    double f = (double)t * g_inv[j];
    // reduce to [0, 2pi): fp32 representation of r then loses < 3e-7 abs
    double r = f - 6.283185307179586476925 * floor(f * 0.15915494309189533577);
    float rf = (float)r;
    g_rc[idx] = cosf(rf);
    g_rs[idx] = sinf(rf);
}

// ---------------- fp32 -> fp16 convert ----------------
__global__ void conv_h_kernel(const float* __restrict__ src, fp16* __restrict__ hi) {
    int i = blockIdx.x * 256 + threadIdx.x;
    float4 v = ((const float4*)src)[i];
    __half2* hp = (__half2*)(hi + (size_t)i * 4);
    hp[0] = __half2(__float2half_rn(v.x), __float2half_rn(v.y));
    hp[1] = __half2(__float2half_rn(v.z), __float2half_rn(v.w));
}

// ---------------- fused W_q|W_k|W_v transpose (fp16) ----------------
__global__ void wtrans_qkv_kernel(const float* __restrict__ Wq,
                                  const float* __restrict__ Wk,
                                  const float* __restrict__ Wv,
                                  fp16* __restrict__ Thi) {
    __shared__ float t[32][33];
    int bx = blockIdx.x;
    const float* W;
    int N, n0, outoff;
    if (bx < 64)      { W = Wq; N = 2048; n0 = bx * 32;        outoff = 0;    }
    else if (bx < 80) { W = Wk; N = 512;  n0 = (bx - 64) * 32; outoff = 2048; }
    else              { W = Wv; N = 512;  n0 = (bx - 80) * 32; outoff = 2560; }
    int k0 = blockIdx.y * 32;
    int tx = threadIdx.x, ty = threadIdx.y;
#pragma unroll
    for (int i = ty; i < 32; i += 8)
        t[i][tx] = W[(size_t)(k0 + i) * N + n0 + tx];
    __syncthreads();
#pragma unroll
    for (int i = ty; i < 32; i += 8)
        Thi[(size_t)(outoff + n0 + i) * KDIM + k0 + tx] = __float2half_rn(t[tx][i]);
}

// ---------------- single W transpose (fp16) ----------------
__global__ void wtrans_kernel(const float* __restrict__ W,
                              fp16* __restrict__ Thi, int N) {
    __shared__ float t[32][33];
    int n0 = blockIdx.x * 32, k0 = blockIdx.y * 32;
    int tx = threadIdx.x, ty = threadIdx.y;
#pragma unroll
    for (int i = ty; i < 32; i += 8)
        t[i][tx] = W[(size_t)(k0 + i) * N + n0 + tx];
    __syncthreads();
#pragma unroll
    for (int i = ty; i < 32; i += 8)
        Thi[(size_t)(n0 + i) * KDIM + k0 + tx] = __float2half_rn(t[tx][i]);
}

// ---------------- HMMA fp16 GEMM (KC=64, 3-stage, occ 2, hoisted addressing) ----------------
#define GEMM_SMEM (3 * 2 * 16384)     // 98304

__device__ __forceinline__ void prefetch_hoisted(
    uint32_t bufb, const char* agb, const char* bgb, uint32_t soff, size_t go) {
#pragma unroll
    for (int i = 0; i < 4; i++) {
        cp16(bufb + soff + i * 4096,         agb + go + (size_t)i * 131072);
        cp16(bufb + 16384 + soff + i * 4096, bgb + go + (size_t)i * 131072);
    }
}

// ropeLimit: apply RoPE to output cols < ropeLimit
__global__ __launch_bounds__(256, 2)
void tc_gemm(const fp16* __restrict__ Ahi, const fp16* __restrict__ Bhi,
             float* __restrict__ C, fp16* __restrict__ Chi,
             int ldC, int ropeLimit) {
    extern __shared__ char sm[];
    uint32_t sb = smem_u32(sm);
    const int tid = threadIdx.x;
    const int wid = tid >> 5, lane = tid & 31;
    const int wm = wid & 3, wn = wid >> 2;
    const int grp = lane >> 2, tig = lane & 3;
    const int bn = blockIdx.x * 128;
    const int bm = blockIdx.y * 128;

    float acc[2][8][4];
#pragma unroll
    for (int i = 0; i < 2; i++)
#pragma unroll
        for (int j = 0; j < 8; j++)
#pragma unroll
            for (int q = 0; q < 4; q++) acc[i][j][q] = 0.f;

    const int lrow = lane & 15;
    const int lhalf = (lane >> 4) & 1;

    const int prow = tid >> 3, pc16 = tid & 7;
    const char* agb = (const char*)(Ahi + (size_t)(bm + prow) * KDIM + pc16 * 8);
    const char* bgb = (const char*)(Bhi + (size_t)(bn + prow) * KDIM + pc16 * 8);
    const uint32_t soff = swz128(prow, pc16);

    prefetch_hoisted(sb,         agb, bgb, soff, 0);
    asm volatile("cp.async.commit_group;");
    prefetch_hoisted(sb + 32768, agb, bgb, soff, (size_t)KC * 2);
    asm volatile("cp.async.commit_group;");

    for (int c = 0; c < NCHUNK; c++) {
        if (c + 1 < NCHUNK) asm volatile("cp.async.wait_group 1;");
        else                asm volatile("cp.async.wait_group 0;");
        __syncthreads();
        if (c + 2 < NCHUNK) {
            prefetch_hoisted(sb + ((c + 2) % 3) * 32768, agb, bgb, soff,
                             (size_t)(c + 2) * KC * 2);
            asm volatile("cp.async.commit_group;");
        }

        uint32_t tb = sb + (c % 3) * 32768;
#pragma unroll
        for (int ka = 0; ka < 4; ka++) {
            int kc16 = ka * 2 + lhalf;
            uint32_t ah[2][4];
#pragma unroll
            for (int i = 0; i < 2; i++) {
                int row = wm * 32 + i * 16 + lrow;
                ldm_x4(ah[i], tb + swz128(row, kc16));
            }
#pragma unroll
            for (int jg = 0; jg < 4; jg++) {
                int row = wn * 64 + jg * 16 + lrow;
                uint32_t bh[4];
                ldm_x4(bh, tb + 16384 + swz128(row, kc16));
#pragma unroll
                for (int jo = 0; jo < 2; jo++) {
                    int j = jg * 2 + jo;
#pragma unroll
                    for (int i = 0; i < 2; i++)
                        mma_f16(acc[i][j], ah[i], bh[jo], bh[jo + 2]);
                }
            }
        }
    }

#pragma unroll
    for (int i = 0; i < 2; i++) {
#pragma unroll
        for (int j = 0; j < 8; j++) {
            int row0 = bm + wm * 32 + i * 16 + grp;
            int row1 = row0 + 8;
            int col  = bn + wn * 64 + j * 8 + tig * 2;
            float c0 = acc[i][j][0], c1 = acc[i][j][1];
            float c2 = acc[i][j][2], c3 = acc[i][j][3];
            if (col < ropeLimit) {
                int jj = (col & 127) >> 1;
                int t0 = row0 & (T_SEQ - 1);
                int t1 = row1 & (T_SEQ - 1);
                float ct0 = g_rc[(t0 << 6) + jj], st0 = g_rs[(t0 << 6) + jj];
                float ct1 = g_rc[(t1 << 6) + jj], st1 = g_rs[(t1 << 6) + jj];
                float e0 = c0, o0 = c1, e1 = c2, o1 = c3;
                c0 = e0 * ct0 - o0 * st0;  c1 = e0 * st0 + o0 * ct0;
                c2 = e1 * ct1 - o1 * st1;  c3 = e1 * st1 + o1 * ct1;
            }
            if (Chi) {
                *(__half2*)(Chi + (size_t)row0 * ldC + col) =
                    __half2(__float2half_rn(c0), __float2half_rn(c1));
                *(__half2*)(Chi + (size_t)row1 * ldC + col) =
                    __half2(__float2half_rn(c2), __float2half_rn(c3));
            } else {
                *(float2*)(C + (size_t)row0 * ldC + col) = make_float2(c0, c1);
                *(float2*)(C + (size_t)row1 * ldC + col) = make_float2(c2, c3);
            }
        }
    }
}

// ---------------- HMMA fp16 flash attention (R15: 64-key tiles, occ 1, Q hoisted) ----------------
// smem: Qhi 32KB + 2 stages x (Khi 16KB + Vhi 16KB) = 98304
#define ATT_SMEM (32768 + 2 * 32768)

__global__ __launch_bounds__(256, 1)
void attn_mma(const fp16* __restrict__ qkvhi, fp16* __restrict__ aoh) {
    extern __shared__ char sm[];
    uint32_t sb = smem_u32(sm);
    const int tid = threadIdx.x, w = tid >> 5, lane = tid & 31;
    const int grp = lane >> 2, tig = lane & 3;
    const int lrow = lane & 15, lhalf = lane >> 4;
    const int qt = (int)gridDim.x - 1 - (int)blockIdx.x;   // largest-work-first
    const int h = blockIdx.y, b = blockIdx.z;
    const int q0 = qt * 128, kvh = h >> 2;
    const float scale = 0.08838834764831845f;
    const float NEG_INF = __int_as_float(0xff800000);

    const uint32_t QH = sb;
    const uint32_t ST = sb + 32768;

    // hoisted per-thread KV addressing: thread step 256 => row += 16
    const int krow = tid >> 4, kc = tid & 15;
    const fp16* kvb = qkvhi + (size_t)b * T_SEQ * LDQKV + 2048 + kvh * DH + kc * 8;
    const uint32_t kvoff = swz256(krow, kc);

    // stage Q tile, then KV tile 0
#pragma unroll
    for (int i = 0; i < 8; i++) {
        int ck = tid + 256 * i;
        int row = ck >> 4, c = ck & 15;
        size_t src = (size_t)(b * T_SEQ + q0 + row) * LDQKV + h * DH + c * 8;
        cp16(QH + swz256(row, c), qkvhi + src);
    }
    asm volatile("cp.async.commit_group;");
    {
#pragma unroll
        for (int i = 0; i < 4; i++) {
            int jg = krow + 16 * i;          // j0 = 0: jg < 128 -> kpos = jg
            const fp16* s = kvb + (size_t)jg * LDQKV;
            cp16(ST + kvoff + i * 4096,         s);         // Khi
            cp16(ST + 16384 + kvoff + i * 4096, s + 512);   // Vhi
        }
        asm volatile("cp.async.commit_group;");
    }

    asm volatile("cp.async.wait_group 1;");
    __syncthreads();
    uint32_t aqh[8][4];
#pragma unroll
    for (int kcq = 0; kcq < 8; kcq++)
        ldm_x4(aqh[kcq], QH + swz256(w * 16 + lrow, kcq * 2 + lhalf));

    float O[16][4];
#pragma unroll
    for (int t = 0; t < 16; t++)
#pragma unroll
        for (int q = 0; q < 4; q++) O[t][q] = 0.f;
    float m0 = NEG_INF, m1 = NEG_INF, l0 = 0.f, l1 = 0.f;

    const int nt = (2 * qt + 2 < 18) ? (2 * qt + 2) : 18;
    const int r0g = q0 + w * 16 + grp;
    const int r1g = r0g + 8;

    for (int jt = 0; jt < nt; jt++) {
        asm volatile("cp.async.wait_group 0;");
        __syncthreads();
        if (jt + 1 < nt) {
            int j0n = (jt + 1) * 64;
            uint32_t dst = ST + ((jt + 1) & 1) * 32768;
#pragma unroll
            for (int i = 0; i < 4; i++) {
                int jg = j0n + krow + 16 * i;
                int kpos = (jg < 128) ? jg : (jg + 896);
                const fp16* s = kvb + (size_t)kpos * LDQKV;
                cp16(dst + kvoff + i * 4096,         s);
                cp16(dst + 16384 + kvoff + i * 4096, s + 512);
            }
            asm volatile("cp.async.commit_group;");
        }

        const int j0 = jt * 64;
        if (j0 <= q0 + w * 16 + 15) {
            uint32_t tb = ST + (jt & 1) * 32768;
            float S[8][4];
#pragma unroll
            for (int t = 0; t < 8; t++)
#pragma unroll
                for (int q = 0; q < 4; q++) S[t][q] = 0.f;

            // S = Qhi Khi^T
#pragma unroll
            for (int kcq = 0; kcq < 8; kcq++) {
#pragma unroll
                for (int g = 0; g < 4; g++) {
                    uint32_t koff = swz256(g * 16 + lrow, kcq * 2 + lhalf);
                    uint32_t bh[4];
                    ldm_x4(bh, tb + koff);
                    mma_f16(S[2*g],   aqh[kcq], bh[0], bh[2]);
                    mma_f16(S[2*g+1], aqh[kcq], bh[1], bh[3]);
                }
            }

            float tm0 = NEG_INF, tm1 = NEG_INF;
#pragma unroll
            for (int t = 0; t < 8; t++) {
                int c0 = j0 + 8 * t + 2 * tig, c1 = c0 + 1;
                S[t][0] = (c0 > r0g) ? NEG_INF : S[t][0] * scale;
                S[t][1] = (c1 > r0g) ? NEG_INF : S[t][1] * scale;
                S[t][2] = (c0 > r1g) ? NEG_INF : S[t][2] * scale;
                S[t][3] = (c1 > r1g) ? NEG_INF : S[t][3] * scale;
                tm0 = fmaxf(tm0, fmaxf(S[t][0], S[t][1]));
                tm1 = fmaxf(tm1, fmaxf(S[t][2], S[t][3]));
            }
            tm0 = fmaxf(tm0, __shfl_xor_sync(0xffffffffu, tm0, 1));
            tm0 = fmaxf(tm0, __shfl_xor_sync(0xffffffffu, tm0, 2));
            tm1 = fmaxf(tm1, __shfl_xor_sync(0xffffffffu, tm1, 1));
            tm1 = fmaxf(tm1, __shfl_xor_sync(0xffffffffu, tm1, 2));
            float mn0 = fmaxf(m0, tm0), mn1 = fmaxf(m1, tm1);
            float al0 = __expf(m0 - mn0), al1 = __expf(m1 - mn1);
            m0 = mn0;  m1 = mn1;
            float rs0 = 0.f, rs1 = 0.f;
#pragma unroll
            for (int t = 0; t < 8; t++) {
                S[t][0] = __expf(S[t][0] - mn0);
                S[t][1] = __expf(S[t][1] - mn0);
                S[t][2] = __expf(S[t][2] - mn1);
                S[t][3] = __expf(S[t][3] - mn1);
                rs0 += S[t][0] + S[t][1];
                rs1 += S[t][2] + S[t][3];
            }
            rs0 += __shfl_xor_sync(0xffffffffu, rs0, 1);
            rs0 += __shfl_xor_sync(0xffffffffu, rs0, 2);
            rs1 += __shfl_xor_sync(0xffffffffu, rs1, 1);
            rs1 += __shfl_xor_sync(0xffffffffu, rs1, 2);
            l0 = l0 * al0 + rs0;
            l1 = l1 * al1 + rs1;
#pragma unroll
            for (int t = 0; t < 16; t++) {
                O[t][0] *= al0;  O[t][1] *= al0;
                O[t][2] *= al1;  O[t][3] *= al1;
            }

            // O += Phi Vhi
#pragma unroll
            for (int kk = 0; kk < 4; kk++) {
                uint32_t pha[4];
#pragma unroll
                for (int half = 0; half < 2; half++) {
                    int t = 2 * kk + half;
                    pha[half * 2 + 0] = packh(S[t][0], S[t][1]);
                    pha[half * 2 + 1] = packh(S[t][2], S[t][3]);
                }
#pragma unroll
                for (int g = 0; g < 8; g++) {
                    uint32_t voff = swz256(kk * 16 + lrow, g * 2 + lhalf);
                    uint32_t vh4[4];
                    ldm_x4t(vh4, tb + 16384 + voff);
                    mma_f16(O[2*g],   pha, vh4[0], vh4[1]);
                    mma_f16(O[2*g+1], pha, vh4[2], vh4[3]);
                }
            }
        }
    }

    float il0 = 1.0f / l0, il1 = 1.0f / l1;
    size_t gr0 = (size_t)(b * T_SEQ + r0g);
    size_t gr1 = (size_t)(b * T_SEQ + r1g);
#pragma unroll
    for (int t = 0; t < 16; t++) {
        int col = h * DH + 8 * t + 2 * tig;
        *(__half2*)(aoh + gr0 * KDIM + col) =
            __half2(__float2half_rn(O[t][0] * il0), __float2half_rn(O[t][1] * il0));
        *(__half2*)(aoh + gr1 * KDIM + col) =
            __half2(__float2half_rn(O[t][2] * il1), __float2half_rn(O[t][3] * il1));
    }
}

// ---------------- launch ----------------
extern "C" void kernel_launch(void* const* d_in, const int* in_sizes, int n_in,
                              void* d_out, int out_size) {
    const float* x  = (const float*)d_in[0];
    const float* Wq = (const float*)d_in[1];
    const float* Wk = (const float*)d_in[2];
    const float* Wv = (const float*)d_in[3];
    const float* Wo = (const float*)d_in[4];
    float* out = (float*)d_out;

    fp16 *xhi, *qkvhi, *aohi, *wqkvth, *woth;
    cudaGetSymbolAddress((void**)&xhi,    g_xhi);
    cudaGetSymbolAddress((void**)&qkvhi,  g_qkvhi);
    cudaGetSymbolAddress((void**)&aohi,   g_aohi);
    cudaGetSymbolAddress((void**)&wqkvth, g_wqkvth);
    cudaGetSymbolAddress((void**)&woth,   g_woth);

    cudaFuncSetAttribute(tc_gemm,  cudaFuncAttributeMaxDynamicSharedMemorySize, GEMM_SMEM);
    cudaFuncSetAttribute(attn_mma, cudaFuncAttributeMaxDynamicSharedMemorySize, ATT_SMEM);

    rope_inv_kernel<<<1, 64>>>();                                            // 0
    rope_table_kernel<<<512, 256>>>();                                       // 1
    conv_h_kernel<<<8192, 256>>>(x, xhi);                                    // 2
    wtrans_qkv_kernel<<<dim3(96, 64), dim3(32, 8)>>>(Wq, Wk, Wv, wqkvth);    // 3
    tc_gemm<<<dim3(24, 32), 256, GEMM_SMEM>>>(xhi, wqkvth,
                                              nullptr, qkvhi, LDQKV, 2560);  // 4
    attn_mma<<<dim3(16, NH, BATCH), 256, ATT_SMEM>>>(qkvhi, aohi);           // 5
    wtrans_kernel<<<dim3(64, 64), dim3(32, 8)>>>(Wo, woth, 2048);            // 6
    tc_gemm<<<dim3(16, 32), 256, GEMM_SMEM>>>(aohi, woth,
                                              out, nullptr, DMODEL, 0);      // 7
}